// round 2
// baseline (speedup 1.0000x reference)
#include <cuda_runtime.h>
#include <cuda_bf16.h>

// <Z_0> after RY·RX on all qubits + CNOT chain reduces analytically to the
// qubit-0 gate only (CNOTs preserve the q0 bit; gates on q1..q15 are
// block-unitary and preserve per-block norms):
//   A = ||u||^2 - ||v||^2,  S = sum(u * conj(v))   (u = top half, v = bottom)
//   <Z_0> = cos^2(t) * A - 2 sin(t) * (Re S + cos(t) * Im S)
// => three fused reductions over 32768 complex pairs per batch row.
//
// R1: split each row over SPLIT blocks to cover all 148 SMs and raise
// aggregate MLP; last-arriving block per row combines partials (fixed-order
// sum => deterministic) and resets the counter for graph replay.

#ifndef QN
#define QN 16
#endif
static constexpr int D     = 1 << QN;      // 65536
static constexpr int HALF  = D >> 1;       // 32768 floats per half-row
static constexpr int HALF4 = HALF >> 2;    // 8192 float4 per half-row
static constexpr int SPLIT = 8;
static constexpr int NT    = 256;
static constexpr int CHUNK4 = HALF4 / SPLIT;        // 1024 float4 per block per array
static constexpr int ITERS  = CHUNK4 / NT;          // 4
static constexpr int MAXB   = 128;

__device__ float    g_part[MAXB * SPLIT * 3];
__device__ unsigned g_cnt[MAXB];            // zero-init at load; reset each launch

__inline__ __device__ float warp_sum(float v) {
    #pragma unroll
    for (int o = 16; o > 0; o >>= 1)
        v += __shfl_down_sync(0xffffffffu, v, o);
    return v;
}

__global__ __launch_bounds__(NT)
void zexp_kernel(const float* __restrict__ re,
                 const float* __restrict__ im,
                 const float* __restrict__ thetas,
                 float* __restrict__ out)
{
    const int row = blockIdx.x;
    const int sp  = blockIdx.y;
    const size_t base  = (size_t)row * D;
    const int    coff  = sp * CHUNK4;

    const float4* __restrict__ ru = (const float4*)(re + base)        + coff;
    const float4* __restrict__ rv = (const float4*)(re + base + HALF) + coff;
    const float4* __restrict__ iu = (const float4*)(im + base)        + coff;
    const float4* __restrict__ iv = (const float4*)(im + base + HALF) + coff;

    float A = 0.f, P = 0.f, Q = 0.f;

    #pragma unroll
    for (int k = 0; k < ITERS; ++k) {
        const int idx = threadIdx.x + k * NT;
        const float4 a = ru[idx];   // u_r
        const float4 b = rv[idx];   // v_r
        const float4 c = iu[idx];   // u_i
        const float4 d = iv[idx];   // v_i

        A += (a.x*a.x + c.x*c.x) - (b.x*b.x + d.x*d.x);
        A += (a.y*a.y + c.y*c.y) - (b.y*b.y + d.y*d.y);
        A += (a.z*a.z + c.z*c.z) - (b.z*b.z + d.z*d.z);
        A += (a.w*a.w + c.w*c.w) - (b.w*b.w + d.w*d.w);

        P += a.x*b.x + c.x*d.x;
        P += a.y*b.y + c.y*d.y;
        P += a.z*b.z + c.z*d.z;
        P += a.w*b.w + c.w*d.w;

        Q += c.x*b.x - a.x*d.x;
        Q += c.y*b.y - a.y*d.y;
        Q += c.z*b.z - a.z*d.z;
        Q += c.w*b.w - a.w*d.w;
    }

    A = warp_sum(A);
    P = warp_sum(P);
    Q = warp_sum(Q);

    __shared__ float sA[NT / 32], sP[NT / 32], sQ[NT / 32];
    const int lane = threadIdx.x & 31;
    const int wid  = threadIdx.x >> 5;
    if (lane == 0) { sA[wid] = A; sP[wid] = P; sQ[wid] = Q; }
    __syncthreads();

    if (threadIdx.x == 0) {
        float tA = 0.f, tP = 0.f, tQ = 0.f;
        #pragma unroll
        for (int w = 0; w < NT / 32; ++w) { tA += sA[w]; tP += sP[w]; tQ += sQ[w]; }

        float* slot = &g_part[(row * SPLIT + sp) * 3];
        slot[0] = tA; slot[1] = tP; slot[2] = tQ;
        __threadfence();

        const unsigned old = atomicAdd(&g_cnt[row], 1u);
        if (old == SPLIT - 1) {
            __threadfence();
            float fA = 0.f, fP = 0.f, fQ = 0.f;
            const float* p = &g_part[row * SPLIT * 3];
            #pragma unroll
            for (int s = 0; s < SPLIT; ++s) {
                fA += p[s * 3 + 0];
                fP += p[s * 3 + 1];
                fQ += p[s * 3 + 2];
            }
            const float t  = thetas[0];
            const float ct = cosf(t);
            const float st = sinf(t);
            out[row] = ct * ct * fA - 2.f * st * (fP + ct * fQ);
            atomicExch(&g_cnt[row], 0u);   // reset for next graph replay
        }
    }
}

extern "C" void kernel_launch(void* const* d_in, const int* in_sizes, int n_in,
                              void* d_out, int out_size)
{
    const float* re     = (const float*)d_in[0];  // states_re (128, 65536)
    const float* im     = (const float*)d_in[1];  // states_im (128, 65536)
    const float* thetas = (const float*)d_in[2];  // (16,)
    float* out = (float*)d_out;                   // (128,)

    const int B = in_sizes[0] / D;                // 128
    dim3 grid(B, SPLIT);
    zexp_kernel<<<grid, NT>>>(re, im, thetas, out);
}